// round 3
// baseline (speedup 1.0000x reference)
#include <cuda_runtime.h>
#include <math.h>

#define B_DIM 2
#define S_LEN 2048
#define H_DIM 4096
#define NH 32
#define HD 128
#define QKV_COLS 12288   // 3*H

// Scratch (no cudaMalloc allowed): qkv = [B*S, 3H], ctx = [B*S, H]
__device__ float g_qkv[(size_t)B_DIM * S_LEN * QKV_COLS];
__device__ float g_ctx[(size_t)B_DIM * S_LEN * H_DIM];

// ---------------------------------------------------------------------------
// GEMM (NT): C[m][n] = sum_k A[m][k] * B[n][k] + bias[n]
// A: MxK row-major, B: NxK row-major, C: MxN row-major.
// 128x128 tile, BK=8, 256 threads, 8x8 register microtile.
// Double-buffered smem (1 barrier per K-step) + register prefetch of the
// next global tile: LDG latency fully hidden under the FFMA block.
// ---------------------------------------------------------------------------
__global__ __launch_bounds__(256) void gemm_nt_kernel(
    const float* __restrict__ A, const float* __restrict__ Bm,
    const float* __restrict__ bias, float* __restrict__ C,
    int M, int N, int K)
{
    __shared__ float As[2][8][132];   // transposed tiles, +4 pad kills STS conflicts
    __shared__ float Bs[2][8][132];

    const int tid  = threadIdx.x;
    const int bm0  = blockIdx.y * 128;
    const int bn0  = blockIdx.x * 128;
    const int ty   = tid >> 4, tx = tid & 15;
    const int row0 = ty * 8,   col0 = tx * 8;
    const int lrow = tid >> 1, lcol = (tid & 1) * 4;

    const float* Ag = A  + (size_t)(bm0 + lrow) * K + lcol;
    const float* Bg = Bm + (size_t)(bn0 + lrow) * K + lcol;

    float acc[8][8];
#pragma unroll
    for (int i = 0; i < 8; i++)
#pragma unroll
        for (int j = 0; j < 8; j++) acc[i][j] = 0.f;

    // Preload tile 0 into buffer 0
    {
        float4 av = *(const float4*)(Ag);
        float4 bv = *(const float4*)(Bg);
        As[0][lcol+0][lrow] = av.x; As[0][lcol+1][lrow] = av.y;
        As[0][lcol+2][lrow] = av.z; As[0][lcol+3][lrow] = av.w;
        Bs[0][lcol+0][lrow] = bv.x; Bs[0][lcol+1][lrow] = bv.y;
        Bs[0][lcol+2][lrow] = bv.z; Bs[0][lcol+3][lrow] = bv.w;
    }
    __syncthreads();

    const int T = K / 8;
    int p = 0;
    for (int t = 0; t < T; t++) {
        float4 av, bv;
        const bool more = (t + 1 < T);
        if (more) {                      // prefetch next tile (regs)
            av = *(const float4*)(Ag + (t + 1) * 8);
            bv = *(const float4*)(Bg + (t + 1) * 8);
        }
#pragma unroll
        for (int kk = 0; kk < 8; kk++) {
            float4 a0 = *(const float4*)(&As[p][kk][row0]);
            float4 a1 = *(const float4*)(&As[p][kk][row0 + 4]);
            float4 b0 = *(const float4*)(&Bs[p][kk][col0]);
            float4 b1 = *(const float4*)(&Bs[p][kk][col0 + 4]);
            float ar[8] = {a0.x, a0.y, a0.z, a0.w, a1.x, a1.y, a1.z, a1.w};
            float br[8] = {b0.x, b0.y, b0.z, b0.w, b1.x, b1.y, b1.z, b1.w};
#pragma unroll
            for (int i = 0; i < 8; i++)
#pragma unroll
                for (int j = 0; j < 8; j++)
                    acc[i][j] += ar[i] * br[j];
        }
        if (more) {                      // store into the idle buffer
            int q = p ^ 1;
            As[q][lcol+0][lrow] = av.x; As[q][lcol+1][lrow] = av.y;
            As[q][lcol+2][lrow] = av.z; As[q][lcol+3][lrow] = av.w;
            Bs[q][lcol+0][lrow] = bv.x; Bs[q][lcol+1][lrow] = bv.y;
            Bs[q][lcol+2][lrow] = bv.z; Bs[q][lcol+3][lrow] = bv.w;
            __syncthreads();             // single barrier per K-step
            p = q;
        }
    }

    float4 bb0 = *(const float4*)(bias + bn0 + col0);
    float4 bb1 = *(const float4*)(bias + bn0 + col0 + 4);
#pragma unroll
    for (int i = 0; i < 8; i++) {
        float* Cp = C + (size_t)(bm0 + row0 + i) * N + bn0 + col0;
        float4 o0 = make_float4(acc[i][0] + bb0.x, acc[i][1] + bb0.y,
                                acc[i][2] + bb0.z, acc[i][3] + bb0.w);
        float4 o1 = make_float4(acc[i][4] + bb1.x, acc[i][5] + bb1.y,
                                acc[i][6] + bb1.z, acc[i][7] + bb1.w);
        *(float4*)Cp       = o0;
        *(float4*)(Cp + 4) = o1;
    }
}

// ---------------------------------------------------------------------------
// RoPE (NeoX style, full head dim) applied in-place to q and k slices of qkv.
// One thread per (b,s,h,i) with i in [0, HD/2); handles both q and k.
// ---------------------------------------------------------------------------
__global__ __launch_bounds__(256) void rope_kernel(
    float* __restrict__ qkv, const int* __restrict__ pos_ids)
{
    int idx = blockIdx.x * 256 + threadIdx.x;        // < B*S*NH*64
    int i  = idx & 63;
    int hh = (idx >> 6) & 31;
    int bs = idx >> 11;

    float pos = (float)pos_ids[bs];
    // inv_freq = 10000^(-2i/128) = exp(-i * ln(10000)/64)
    float inv = expf(-0.14391156832239707f * (float)i);
    float ang = pos * inv;
    float sn, cs;
    sincosf(ang, &sn, &cs);

    float* qp = qkv + (size_t)bs * QKV_COLS + hh * HD;
    float x1 = qp[i], x2 = qp[i + 64];
    qp[i]      = x1 * cs - x2 * sn;
    qp[i + 64] = x2 * cs + x1 * sn;

    float* kp = qp + H_DIM;
    x1 = kp[i]; x2 = kp[i + 64];
    kp[i]      = x1 * cs - x2 * sn;
    kp[i + 64] = x2 * cs + x1 * sn;
}

// ---------------------------------------------------------------------------
// Causal flash attention, fp32. 64x64 tiles, 256 threads.
// Q,K stored transposed in smem ([d][r], stride 68) for conflict-free QK^T.
// V row-major; PV uses interleaved d-mapping (d = 4*c4 + 16u + e).
// ---------------------------------------------------------------------------
#define ATT_SMEM_FLOATS (128*68 + 128*68 + 64*128 + 64*68 + 64*4 + 64*3)

__global__ __launch_bounds__(256) void attn_kernel(
    const float* __restrict__ qkv, float* __restrict__ ctx)
{
    extern __shared__ float sm[];
    float* Qt  = sm;                 // [128][68]
    float* Kt  = Qt + 128 * 68;      // [128][68]
    float* Vs  = Kt + 128 * 68;      // [64][128]
    float* Ss  = Vs + 64 * 128;      // [64][68]
    float* red = Ss + 64 * 68;       // [64][4]
    float* m_s = red + 64 * 4;       // [64]
    float* l_s = m_s + 64;           // [64]
    float* a_s = l_s + 64;           // [64]

    const int qt = blockIdx.x, h = blockIdx.y, b = blockIdx.z;
    const int tid = threadIdx.x;
    const int q0 = qt * 64;

    const int rr = tid >> 2;         // 0..63 (row for load/softmax/PV)
    const int c4 = tid & 3;
    const int d0 = c4 * 32;

    // Load Q tile transposed
    {
        const float* gq = qkv + (size_t)(b * S_LEN + q0 + rr) * QKV_COLS + h * HD;
#pragma unroll
        for (int u = 0; u < 8; u++) {
            int d = d0 + 4 * u;
            float4 v = *(const float4*)(gq + d);
            Qt[(d + 0) * 68 + rr] = v.x;
            Qt[(d + 1) * 68 + rr] = v.y;
            Qt[(d + 2) * 68 + rr] = v.z;
            Qt[(d + 3) * 68 + rr] = v.w;
        }
    }
    if (tid < 64) { m_s[tid] = -1e30f; l_s[tid] = 0.f; }

    float acc[32];
#pragma unroll
    for (int m = 0; m < 32; m++) acc[m] = 0.f;

    const float scale = 0.08838834764831845f;   // 1/sqrt(128)

    for (int kt = 0; kt <= qt; kt++) {
        __syncthreads();   // protects Qt/m_s init (iter 0) and K/V/Ss reuse
        // Load K transposed + V
        {
            const float* gk = qkv + (size_t)(b * S_LEN + kt * 64 + rr) * QKV_COLS
                              + h * HD + H_DIM;
#pragma unroll
            for (int u = 0; u < 8; u++) {
                int d = d0 + 4 * u;
                float4 v = *(const float4*)(gk + d);
                Kt[(d + 0) * 68 + rr] = v.x;
                Kt[(d + 1) * 68 + rr] = v.y;
                Kt[(d + 2) * 68 + rr] = v.z;
                Kt[(d + 3) * 68 + rr] = v.w;
            }
            const float4* gv4 = (const float4*)(gk + H_DIM);
            float4* vrow = (float4*)(Vs + rr * HD);
#pragma unroll
            for (int u = 0; u < 8; u++)
                vrow[(d0 >> 2) + u] = gv4[(d0 >> 2) + u];
        }
        __syncthreads();
        // S = scale * Q K^T  (+ causal mask on the diagonal tile)
        {
            const int tr = tid >> 4, tc = tid & 15;
            float sa[16];
#pragma unroll
            for (int i = 0; i < 16; i++) sa[i] = 0.f;
#pragma unroll 4
            for (int d = 0; d < HD; d++) {
                float4 qa = *(const float4*)(Qt + d * 68 + tr * 4);
                float4 kb = *(const float4*)(Kt + d * 68 + tc * 4);
                float aq[4] = {qa.x, qa.y, qa.z, qa.w};
                float bk[4] = {kb.x, kb.y, kb.z, kb.w};
#pragma unroll
                for (int i = 0; i < 4; i++)
#pragma unroll
                    for (int j = 0; j < 4; j++)
                        sa[i * 4 + j] += aq[i] * bk[j];
            }
            const bool diag = (kt == qt);
#pragma unroll
            for (int i = 0; i < 4; i++) {
                int r = tr * 4 + i;
#pragma unroll
                for (int j = 0; j < 4; j++) {
                    int c = tc * 4 + j;
                    float v = sa[i * 4 + j] * scale;
                    if (diag && c > r) v = -1e30f;
                    Ss[r * 68 + c] = v;
                }
            }
        }
        __syncthreads();
        // Online softmax: partial max
        {
            float pm = -1e30f;
#pragma unroll
            for (int jj = 0; jj < 16; jj++)
                pm = fmaxf(pm, Ss[rr * 68 + c4 * 16 + jj]);
            red[rr * 4 + c4] = pm;
        }
        __syncthreads();
        if (tid < 64) {
            float mt = fmaxf(fmaxf(red[tid*4+0], red[tid*4+1]),
                             fmaxf(red[tid*4+2], red[tid*4+3]));
            float mo = m_s[tid];
            float mn = fmaxf(mo, mt);
            a_s[tid] = __expf(mo - mn);
            m_s[tid] = mn;
        }
        __syncthreads();
        // exp + partial sum (spread across all 256 threads for MUFU rate)
        {
            float mn = m_s[rr];
            float ps = 0.f;
#pragma unroll
            for (int jj = 0; jj < 16; jj++) {
                float p = __expf(Ss[rr * 68 + c4 * 16 + jj] - mn);
                Ss[rr * 68 + c4 * 16 + jj] = p;
                ps += p;
            }
            red[rr * 4 + c4] = ps;
        }
        __syncthreads();
        if (tid < 64)
            l_s[tid] = l_s[tid] * a_s[tid]
                     + (red[tid*4+0] + red[tid*4+1] + red[tid*4+2] + red[tid*4+3]);
        // PV accumulate: O[rr][d] = O*alpha + sum_j p[rr][j] * V[j][d]
        {
            float alpha = a_s[rr];
#pragma unroll
            for (int m = 0; m < 32; m++) acc[m] *= alpha;
            const float4* Vs4 = (const float4*)Vs;
#pragma unroll 2
            for (int j = 0; j < 64; j++) {
                float p = Ss[rr * 68 + j];
#pragma unroll
                for (int u = 0; u < 8; u++) {
                    float4 v = Vs4[j * 32 + c4 + 4 * u];
                    acc[u*4+0] += p * v.x;
                    acc[u*4+1] += p * v.y;
                    acc[u*4+2] += p * v.z;
                    acc[u*4+3] += p * v.w;
                }
            }
        }
    }
    __syncthreads();   // l_s final visible to all
    {
        float inv_l = 1.0f / l_s[rr];
        float* go = ctx + (size_t)(b * S_LEN + q0 + rr) * H_DIM + h * HD;
#pragma unroll
        for (int u = 0; u < 8; u++) {
            float4 o;
            o.x = acc[u*4+0] * inv_l;
            o.y = acc[u*4+1] * inv_l;
            o.z = acc[u*4+2] * inv_l;
            o.w = acc[u*4+3] * inv_l;
            *(float4*)(go + 4 * c4 + 16 * u) = o;   // d = 4*c4 + 16u + e
        }
    }
}

// ---------------------------------------------------------------------------
extern "C" void kernel_launch(void* const* d_in, const int* in_sizes, int n_in,
                              void* d_out, int out_size)
{
    const int*   pos    = (const int*)  d_in[0];
    const float* hidden = (const float*)d_in[1];
    const float* w_qkv  = (const float*)d_in[2];
    const float* b_qkv  = (const float*)d_in[3];
    const float* w_out  = (const float*)d_in[4];
    const float* b_out  = (const float*)d_in[5];
    float* out = (float*)d_out;

    void *p1, *p2;
    cudaGetSymbolAddress(&p1, g_qkv);
    cudaGetSymbolAddress(&p2, g_ctx);
    float* qkv = (float*)p1;
    float* ctx = (float*)p2;

    const int M = B_DIM * S_LEN;   // 4096

    // 1) QKV projection: [4096,4096] x [12288,4096]^T -> [4096,12288]
    gemm_nt_kernel<<<dim3(QKV_COLS / 128, M / 128), 256>>>(
        hidden, w_qkv, b_qkv, qkv, M, QKV_COLS, H_DIM);

    // 2) RoPE on q and k (in place)
    rope_kernel<<<(B_DIM * S_LEN * NH * (HD / 2)) / 256, 256>>>(qkv, pos);

    // 3) Causal flash attention -> ctx [4096, 4096]
    size_t smem = ATT_SMEM_FLOATS * sizeof(float);   // 121600 B
    cudaFuncSetAttribute(attn_kernel,
                         cudaFuncAttributeMaxDynamicSharedMemorySize, (int)smem);
    attn_kernel<<<dim3(S_LEN / 64, NH, B_DIM), 256, smem>>>(qkv, ctx);

    // 4) Output projection: [4096,4096] x [4096,4096]^T -> d_out
    gemm_nt_kernel<<<dim3(H_DIM / 128, M / 128), 256>>>(
        ctx, w_out, b_out, out, M, H_DIM, H_DIM);
}

// round 11
// speedup vs baseline: 1.8924x; 1.8924x over previous
#include <cuda_runtime.h>
#include <cuda_bf16.h>
#include <math.h>
#include <stdint.h>

#define B_DIM 2
#define S_LEN 2048
#define H_DIM 4096
#define NH 32
#define HD 128
#define QKV_COLS 12288   // 3*H
#define GK 4096          // GEMM K

// ---------------------------------------------------------------------------
// Scratch (__device__ globals; no cudaMalloc allowed)
// ---------------------------------------------------------------------------
__device__ float g_qkv[(size_t)B_DIM * S_LEN * QKV_COLS];
__device__ float g_ctx[(size_t)B_DIM * S_LEN * H_DIM];
__device__ __nv_bfloat16 g_hid_hi[(size_t)B_DIM * S_LEN * H_DIM];
__device__ __nv_bfloat16 g_hid_lo[(size_t)B_DIM * S_LEN * H_DIM];
__device__ __nv_bfloat16 g_wqkv_hi[(size_t)QKV_COLS * H_DIM];
__device__ __nv_bfloat16 g_wqkv_lo[(size_t)QKV_COLS * H_DIM];
__device__ __nv_bfloat16 g_wout_hi[(size_t)H_DIM * H_DIM];
__device__ __nv_bfloat16 g_wout_lo[(size_t)H_DIM * H_DIM];
__device__ __nv_bfloat16 g_ctx_hi[(size_t)B_DIM * S_LEN * H_DIM];
__device__ __nv_bfloat16 g_ctx_lo[(size_t)B_DIM * S_LEN * H_DIM];

// ---------------------------------------------------------------------------
// Helpers (sm_80-era PTX only — NO tcgen05, harness ptxas targets sm_103 base)
// ---------------------------------------------------------------------------
__device__ __forceinline__ uint32_t smem_u32(const void* p) {
    uint32_t a;
    asm("{ .reg .u64 t; cvta.to.shared.u64 t, %1; cvt.u32.u64 %0, t; }"
        : "=r"(a) : "l"(p));
    return a;
}

#define CP_ASYNC16(dst, src) \
    asm volatile("cp.async.cg.shared.global [%0], [%1], 16;" \
                 :: "r"((uint32_t)(dst)), "l"(src) : "memory")
#define CP_ASYNC_COMMIT() asm volatile("cp.async.commit_group;" ::: "memory")
#define CP_ASYNC_WAIT2()  asm volatile("cp.async.wait_group 2;" ::: "memory")

__device__ __forceinline__ void ldmat_x4(uint32_t& r0, uint32_t& r1,
                                         uint32_t& r2, uint32_t& r3,
                                         uint32_t addr) {
    asm volatile("ldmatrix.sync.aligned.m8n8.x4.shared.b16 {%0,%1,%2,%3}, [%4];"
                 : "=r"(r0), "=r"(r1), "=r"(r2), "=r"(r3) : "r"(addr));
}

__device__ __forceinline__ void mma_16816(float* c, const uint32_t* a,
                                          uint32_t b0, uint32_t b1) {
    asm volatile(
        "mma.sync.aligned.m16n8k16.row.col.f32.bf16.bf16.f32 "
        "{%0,%1,%2,%3}, {%4,%5,%6,%7}, {%8,%9}, {%0,%1,%2,%3};"
        : "+f"(c[0]), "+f"(c[1]), "+f"(c[2]), "+f"(c[3])
        : "r"(a[0]), "r"(a[1]), "r"(a[2]), "r"(a[3]), "r"(b0), "r"(b1));
}

// ---------------------------------------------------------------------------
// fp32 -> (hi, lo) bf16 split
// ---------------------------------------------------------------------------
__global__ __launch_bounds__(256) void split_bf16_kernel(
    const float* __restrict__ x, __nv_bfloat16* __restrict__ hi,
    __nv_bfloat16* __restrict__ lo, int n4)
{
    int i = blockIdx.x * 256 + threadIdx.x;
    if (i >= n4) return;
    float4 v = ((const float4*)x)[i];
    __nv_bfloat16 h0 = __float2bfloat16_rn(v.x);
    __nv_bfloat16 h1 = __float2bfloat16_rn(v.y);
    __nv_bfloat16 h2 = __float2bfloat16_rn(v.z);
    __nv_bfloat16 h3 = __float2bfloat16_rn(v.w);
    __nv_bfloat16 l0 = __float2bfloat16_rn(v.x - __bfloat162float(h0));
    __nv_bfloat16 l1 = __float2bfloat16_rn(v.y - __bfloat162float(h1));
    __nv_bfloat16 l2 = __float2bfloat16_rn(v.z - __bfloat162float(h2));
    __nv_bfloat16 l3 = __float2bfloat16_rn(v.w - __bfloat162float(h3));
    uint2 hp, lp;
    hp.x = ((uint32_t)__bfloat16_as_ushort(h1) << 16) | __bfloat16_as_ushort(h0);
    hp.y = ((uint32_t)__bfloat16_as_ushort(h3) << 16) | __bfloat16_as_ushort(h2);
    lp.x = ((uint32_t)__bfloat16_as_ushort(l1) << 16) | __bfloat16_as_ushort(l0);
    lp.y = ((uint32_t)__bfloat16_as_ushort(l3) << 16) | __bfloat16_as_ushort(l2);
    ((uint2*)hi)[i] = hp;
    ((uint2*)lo)[i] = lp;
}

// ---------------------------------------------------------------------------
// HMMA GEMM (NT), 3-term bf16 split: C = Ah.Bh^T + Ah.Bl^T + Al.Bh^T + bias
// 128x128 CTA tile, 8 warps (warp tile 32x64, m16n8k16 atoms), BK=32,
// 4-stage cp.async pipeline with depth-2 lookahead (one barrier per stage).
// A*: [M,K] bf16 row-major.  B*: [N,K] bf16 row-major.  C: [M,N] fp32.
// ---------------------------------------------------------------------------
#define BKG 32
#define TSP (GK / BKG)           // 128 stages per pass
#define TST (3 * TSP)            // 384 stages total
#define LDSW 40                  // padded row stride in halves (80B)
#define TILE_B (128 * LDSW * 2)  // 10240 B per tile
#define STG_B  (2 * TILE_B)      // A+B per stage = 20480 B
#define GEMM_SMEM (4 * STG_B)    // 81920 B

__global__ __launch_bounds__(256, 1) void gemm_hmma_kernel(
    const __nv_bfloat16* __restrict__ Ah, const __nv_bfloat16* __restrict__ Al,
    const __nv_bfloat16* __restrict__ Bh, const __nv_bfloat16* __restrict__ Bl,
    const float* __restrict__ bias, float* __restrict__ C, int N)
{
    extern __shared__ char smem[];
    const uint32_t sbase = smem_u32(smem);

    const int tid = threadIdx.x;
    const int lane = tid & 31, wid = tid >> 5;
    const int warp_m = wid & 3;          // 4 warps along M (32 rows each)
    const int warp_n = wid >> 2;         // 2 warps along N (64 cols each)
    const int m0 = blockIdx.y * 128;
    const int n0 = blockIdx.x * 128;

    // cp.async mapping: 512 16B-chunks per tile; thread t handles chunks t, t+256
    const int lr = tid >> 2;             // 0..63
    const int lc4 = tid & 3;             // 0..3 (16B column)
    const uint32_t soff0 = (uint32_t)(lr * 80 + lc4 * 16);
    const uint32_t soff1 = (uint32_t)((lr + 64) * 80 + lc4 * 16);

    auto issue_stage = [&](int s) {
        const int p = s / TSP;           // pass: 0=Ah.Bh 1=Ah.Bl 2=Al.Bh
        const int kc = (s - p * TSP) * BKG;
        const __nv_bfloat16* As = (p < 2) ? Ah : Al;
        const __nv_bfloat16* Bs = (p == 1) ? Bl : Bh;
        const uint32_t sa = sbase + (uint32_t)(s & 3) * STG_B;
        const uint32_t sb = sa + TILE_B;
        const __nv_bfloat16* ga0 = As + (size_t)(m0 + lr) * GK + kc + lc4 * 8;
        const __nv_bfloat16* gb0 = Bs + (size_t)(n0 + lr) * GK + kc + lc4 * 8;
        CP_ASYNC16(sa + soff0, ga0);
        CP_ASYNC16(sa + soff1, ga0 + (size_t)64 * GK);
        CP_ASYNC16(sb + soff0, gb0);
        CP_ASYNC16(sb + soff1, gb0 + (size_t)64 * GK);
    };

    float acc[2][8][4];
#pragma unroll
    for (int i = 0; i < 2; i++)
#pragma unroll
        for (int j = 0; j < 8; j++)
#pragma unroll
            for (int k = 0; k < 4; k++) acc[i][j][k] = 0.f;

    // ldmatrix lane-derived offsets (bytes, within tile)
    // A (m16k16, x4): lanes 0-15 -> rows 0-15 @k0; lanes 16-31 -> rows @k+8
    const uint32_t a_loff = (uint32_t)((warp_m * 32 + (lane & 15)) * 80
                                       + (lane >> 4) * 16);
    // B (n16k16, x4): groups of 8 lanes -> (n0-7,k0),(n0-7,k8),(n8-15,k0),(n8-15,k8)
    const uint32_t b_loff = (uint32_t)((warp_n * 64 + ((lane >> 4) * 8 + (lane & 7))) * 80
                                       + ((lane >> 3) & 1) * 16);

    // Prologue: stages 0,1 in flight
    issue_stage(0); CP_ASYNC_COMMIT();
    issue_stage(1); CP_ASYNC_COMMIT();

    for (int t = 0; t < TST; t++) {
        if (t + 2 < TST) issue_stage(t + 2);
        CP_ASYNC_COMMIT();
        CP_ASYNC_WAIT2();        // stage t resident (2 newer groups may be in flight)
        __syncthreads();         // all threads' copies visible; slot (t+2)%4 != t%4

        const uint32_t sa = sbase + (uint32_t)(t & 3) * STG_B;
        const uint32_t sb = sa + TILE_B;
#pragma unroll
        for (int k16 = 0; k16 < 2; k16++) {
            const uint32_t kb = (uint32_t)(k16 * 32);   // 16 halves = 32B
            uint32_t a[2][4];
            ldmat_x4(a[0][0], a[0][1], a[0][2], a[0][3], sa + a_loff + kb);
            ldmat_x4(a[1][0], a[1][1], a[1][2], a[1][3],
                     sa + a_loff + kb + 16 * 80);
            uint32_t bf[8][2];
#pragma unroll
            for (int nf16 = 0; nf16 < 4; nf16++) {
                uint32_t r0, r1, r2, r3;
                ldmat_x4(r0, r1, r2, r3,
                         sb + b_loff + kb + (uint32_t)(nf16 * 16 * 80));
                bf[nf16 * 2 + 0][0] = r0; bf[nf16 * 2 + 0][1] = r1;
                bf[nf16 * 2 + 1][0] = r2; bf[nf16 * 2 + 1][1] = r3;
            }
#pragma unroll
            for (int mf = 0; mf < 2; mf++)
#pragma unroll
                for (int nf = 0; nf < 8; nf++)
                    mma_16816(acc[mf][nf], a[mf], bf[nf][0], bf[nf][1]);
        }
    }

    // Epilogue: acc -> C (+bias).  c0,c1: row=t/4, col=2(t%4); c2,c3: row+8.
    {
        const int rbase = m0 + warp_m * 32 + (lane >> 2);
        const int cbase = n0 + warp_n * 64 + 2 * (lane & 3);
#pragma unroll
        for (int mf = 0; mf < 2; mf++) {
#pragma unroll
            for (int nf = 0; nf < 8; nf++) {
                const int col = cbase + nf * 8;
                const float2 bv = *(const float2*)(bias + col);
                const int r0 = rbase + mf * 16;
                float2 o0, o1;
                o0.x = acc[mf][nf][0] + bv.x; o0.y = acc[mf][nf][1] + bv.y;
                o1.x = acc[mf][nf][2] + bv.x; o1.y = acc[mf][nf][3] + bv.y;
                *(float2*)(C + (size_t)r0 * N + col)       = o0;
                *(float2*)(C + (size_t)(r0 + 8) * N + col) = o1;
            }
        }
    }
}

// ---------------------------------------------------------------------------
// RoPE (NeoX style, full head dim) in-place on q and k slices of qkv.
// ---------------------------------------------------------------------------
__global__ __launch_bounds__(256) void rope_kernel(
    float* __restrict__ qkv, const int* __restrict__ pos_ids)
{
    int idx = blockIdx.x * 256 + threadIdx.x;        // < B*S*NH*64
    int i  = idx & 63;
    int hh = (idx >> 6) & 31;
    int bs = idx >> 11;

    float pos = (float)pos_ids[bs];
    float inv = expf(-0.14391156832239707f * (float)i);  // 10000^(-i/64)
    float ang = pos * inv;
    float sn, cs;
    sincosf(ang, &sn, &cs);

    float* qp = qkv + (size_t)bs * QKV_COLS + hh * HD;
    float x1 = qp[i], x2 = qp[i + 64];
    qp[i]      = x1 * cs - x2 * sn;
    qp[i + 64] = x2 * cs + x1 * sn;

    float* kp = qp + H_DIM;
    x1 = kp[i]; x2 = kp[i + 64];
    kp[i]      = x1 * cs - x2 * sn;
    kp[i + 64] = x2 * cs + x1 * sn;
}

// ---------------------------------------------------------------------------
// Causal flash attention, fp32. 64x64 tiles, 256 threads. (known-good control)
// ---------------------------------------------------------------------------
#define ATT_SMEM_FLOATS (128*68 + 128*68 + 64*128 + 64*68 + 64*4 + 64*3)

__global__ __launch_bounds__(256) void attn_kernel(
    const float* __restrict__ qkv, float* __restrict__ ctx)
{
    extern __shared__ float sm[];
    float* Qt  = sm;                 // [128][68]
    float* Kt  = Qt + 128 * 68;      // [128][68]
    float* Vs  = Kt + 128 * 68;      // [64][128]
    float* Ss  = Vs + 64 * 128;      // [64][68]
    float* red = Ss + 64 * 68;       // [64][4]
    float* m_s = red + 64 * 4;       // [64]
    float* l_s = m_s + 64;           // [64]
    float* a_s = l_s + 64;           // [64]

    const int qt = blockIdx.x, h = blockIdx.y, b = blockIdx.z;
    const int tid = threadIdx.x;
    const int q0 = qt * 64;

    const int rr = tid >> 2;
    const int c4 = tid & 3;
    const int d0 = c4 * 32;

    {
        const float* gq = qkv + (size_t)(b * S_LEN + q0 + rr) * QKV_COLS + h * HD;
#pragma unroll
        for (int u = 0; u < 8; u++) {
            int d = d0 + 4 * u;
            float4 v = *(const float4*)(gq + d);
            Qt[(d + 0) * 68 + rr] = v.x;
            Qt[(d + 1) * 68 + rr] = v.y;
            Qt[(d + 2) * 68 + rr] = v.z;
            Qt[(d + 3) * 68 + rr] = v.w;
        }
    }
    if (tid < 64) { m_s[tid] = -1e30f; l_s[tid] = 0.f; }

    float acc[32];
#pragma unroll
    for (int m = 0; m < 32; m++) acc[m] = 0.f;

    const float scale = 0.08838834764831845f;

    for (int kt = 0; kt <= qt; kt++) {
        __syncthreads();
        {
            const float* gk = qkv + (size_t)(b * S_LEN + kt * 64 + rr) * QKV_COLS
                              + h * HD + H_DIM;
#pragma unroll
            for (int u = 0; u < 8; u++) {
                int d = d0 + 4 * u;
                float4 v = *(const float4*)(gk + d);
                Kt[(d + 0) * 68 + rr] = v.x;
                Kt[(d + 1) * 68 + rr] = v.y;
                Kt[(d + 2) * 68 + rr] = v.z;
                Kt[(d + 3) * 68 + rr] = v.w;
            }
            const float4* gv4 = (const float4*)(gk + H_DIM);
            float4* vrow = (float4*)(Vs + rr * HD);
#pragma unroll
            for (int u = 0; u < 8; u++)
                vrow[(d0 >> 2) + u] = gv4[(d0 >> 2) + u];
        }
        __syncthreads();
        {
            const int tr = tid >> 4, tc = tid & 15;
            float sa[16];
#pragma unroll
            for (int i = 0; i < 16; i++) sa[i] = 0.f;
#pragma unroll 4
            for (int d = 0; d < HD; d++) {
                float4 qa = *(const float4*)(Qt + d * 68 + tr * 4);
                float4 kb = *(const float4*)(Kt + d * 68 + tc * 4);
                float aq[4] = {qa.x, qa.y, qa.z, qa.w};
                float bk[4] = {kb.x, kb.y, kb.z, kb.w};
#pragma unroll
                for (int i = 0; i < 4; i++)
#pragma unroll
                    for (int j = 0; j < 4; j++)
                        sa[i * 4 + j] += aq[i] * bk[j];
            }
            const bool diag = (kt == qt);
#pragma unroll
            for (int i = 0; i < 4; i++) {
                int r = tr * 4 + i;
#pragma unroll
                for (int j = 0; j < 4; j++) {
                    int c = tc * 4 + j;
                    float v = sa[i * 4 + j] * scale;
                    if (diag && c > r) v = -1e30f;
                    Ss[r * 68 + c] = v;
                }
            }
        }
        __syncthreads();
        {
            float pm = -1e30f;
#pragma unroll
            for (int jj = 0; jj < 16; jj++)
                pm = fmaxf(pm, Ss[rr * 68 + c4 * 16 + jj]);
            red[rr * 4 + c4] = pm;
        }
        __syncthreads();
        if (tid < 64) {
            float mt = fmaxf(fmaxf(red[tid*4+0], red[tid*4+1]),
                             fmaxf(red[tid*4+2], red[tid*4+3]));
            float mo = m_s[tid];
            float mn = fmaxf(mo, mt);
            a_s[tid] = __expf(mo - mn);
            m_s[tid] = mn;
        }
        __syncthreads();
        {
            float mn = m_s[rr];
            float ps = 0.f;
#pragma unroll
            for (int jj = 0; jj < 16; jj++) {
                float p = __expf(Ss[rr * 68 + c4 * 16 + jj] - mn);
                Ss[rr * 68 + c4 * 16 + jj] = p;
                ps += p;
            }
            red[rr * 4 + c4] = ps;
        }
        __syncthreads();
        if (tid < 64)
            l_s[tid] = l_s[tid] * a_s[tid]
                     + (red[tid*4+0] + red[tid*4+1] + red[tid*4+2] + red[tid*4+3]);
        {
            float alpha = a_s[rr];
#pragma unroll
            for (int m = 0; m < 32; m++) acc[m] *= alpha;
            const float4* Vs4 = (const float4*)Vs;
#pragma unroll 2
            for (int j = 0; j < 64; j++) {
                float p = Ss[rr * 68 + j];
#pragma unroll
                for (int u = 0; u < 8; u++) {
                    float4 v = Vs4[j * 32 + c4 + 4 * u];
                    acc[u*4+0] += p * v.x;
                    acc[u*4+1] += p * v.y;
                    acc[u*4+2] += p * v.z;
                    acc[u*4+3] += p * v.w;
                }
            }
        }
    }
    __syncthreads();
    {
        float inv_l = 1.0f / l_s[rr];
        float* go = ctx + (size_t)(b * S_LEN + q0 + rr) * H_DIM + h * HD;
#pragma unroll
        for (int u = 0; u < 8; u++) {
            float4 o;
            o.x = acc[u*4+0] * inv_l;
            o.y = acc[u*4+1] * inv_l;
            o.z = acc[u*4+2] * inv_l;
            o.w = acc[u*4+3] * inv_l;
            *(float4*)(go + 4 * c4 + 16 * u) = o;
        }
    }
}

// ---------------------------------------------------------------------------
extern "C" void kernel_launch(void* const* d_in, const int* in_sizes, int n_in,
                              void* d_out, int out_size)
{
    const int*   pos    = (const int*)  d_in[0];
    const float* hidden = (const float*)d_in[1];
    const float* w_qkv  = (const float*)d_in[2];
    const float* b_qkv  = (const float*)d_in[3];
    const float* w_out  = (const float*)d_in[4];
    const float* b_out  = (const float*)d_in[5];
    float* out = (float*)d_out;

    void *pq, *pc, *phh, *phl, *pwh, *pwl, *poh, *pol, *pch, *pcl;
    cudaGetSymbolAddress(&pq,  g_qkv);
    cudaGetSymbolAddress(&pc,  g_ctx);
    cudaGetSymbolAddress(&phh, g_hid_hi);
    cudaGetSymbolAddress(&phl, g_hid_lo);
    cudaGetSymbolAddress(&pwh, g_wqkv_hi);
    cudaGetSymbolAddress(&pwl, g_wqkv_lo);
    cudaGetSymbolAddress(&poh, g_wout_hi);
    cudaGetSymbolAddress(&pol, g_wout_lo);
    cudaGetSymbolAddress(&pch, g_ctx_hi);
    cudaGetSymbolAddress(&pcl, g_ctx_lo);
    float* qkv = (float*)pq;
    float* ctx = (float*)pc;

    const int M = B_DIM * S_LEN;               // 4096
    const int nh  = M * H_DIM / 4;
    const int nwq = QKV_COLS * H_DIM / 4;
    const int nwo = H_DIM * H_DIM / 4;

    cudaFuncSetAttribute(gemm_hmma_kernel,
                         cudaFuncAttributeMaxDynamicSharedMemorySize, GEMM_SMEM);
    cudaFuncSetAttribute(attn_kernel,
                         cudaFuncAttributeMaxDynamicSharedMemorySize,
                         (int)(ATT_SMEM_FLOATS * sizeof(float)));

    // 1) bf16 hi/lo splits of activations and weights
    split_bf16_kernel<<<(nh  + 255) / 256, 256>>>(hidden, (__nv_bfloat16*)phh,
                                                  (__nv_bfloat16*)phl, nh);
    split_bf16_kernel<<<(nwq + 255) / 256, 256>>>(w_qkv, (__nv_bfloat16*)pwh,
                                                  (__nv_bfloat16*)pwl, nwq);
    split_bf16_kernel<<<(nwo + 255) / 256, 256>>>(w_out, (__nv_bfloat16*)poh,
                                                  (__nv_bfloat16*)pol, nwo);

    // 2) QKV projection (HMMA): [4096,4096] x [12288,4096]^T
    gemm_hmma_kernel<<<dim3(QKV_COLS / 128, M / 128), 256, GEMM_SMEM>>>(
        (const __nv_bfloat16*)phh, (const __nv_bfloat16*)phl,
        (const __nv_bfloat16*)pwh, (const __nv_bfloat16*)pwl,
        b_qkv, qkv, QKV_COLS);

    // 3) RoPE on q and k (in place)
    rope_kernel<<<(B_DIM * S_LEN * NH * (HD / 2)) / 256, 256>>>(qkv, pos);

    // 4) Causal flash attention -> ctx
    attn_kernel<<<dim3(S_LEN / 64, NH, B_DIM), 256,
                  ATT_SMEM_FLOATS * sizeof(float)>>>(qkv, ctx);

    // 5) split ctx, then output projection (HMMA) -> d_out
    split_bf16_kernel<<<(nh + 255) / 256, 256>>>(ctx, (__nv_bfloat16*)pch,
                                                 (__nv_bfloat16*)pcl, nh);
    gemm_hmma_kernel<<<dim3(H_DIM / 128, M / 128), 256, GEMM_SMEM>>>(
        (const __nv_bfloat16*)pch, (const __nv_bfloat16*)pcl,
        (const __nv_bfloat16*)poh, (const __nv_bfloat16*)pol,
        b_out, out, H_DIM);
}